// round 1
// baseline (speedup 1.0000x reference)
#include <cuda_runtime.h>
#include <cuda_bf16.h>
#include <math.h>

// ---------------------------------------------------------------------------
// ComplexExponentialPositionalEncoding
// out[i,j,:] = (enc_i[i,:] + enc_j[j,:]) * (1 + 0.1*sqrt((i/1000)^2 + (j/1000)^2))
// enc_x[p, 2k] = cos(p * freqs_x[k]); enc_x[p, 2k+1] = sin(p * freqs_x[k])
// H=W=384, D=1024 -> 604MB fp32 output. Pure HBM-store-bound.
// ---------------------------------------------------------------------------

#define MAXN 1024            // max height/width supported (MAX_SEQ_LEN=1000)
#define MAXD 2048            // max embed dim supported
#define TI 4
#define TJ 4

__device__ float g_enc_i[(size_t)MAXN * MAXD];
__device__ float g_enc_j[(size_t)MAXN * MAXD];

// height/width are device scalars of unknown exact dtype (int32/int64/float32).
// Sniff: small positive int32 wins; otherwise try float reinterpretation.
__device__ __forceinline__ int read_dim(const void* p) {
    int v = *(const int*)p;                 // int32, or low word of int64 (LE)
    if (v > 0 && v <= 1000000) return v;
    float f = *(const float*)p;
    if (f >= 1.0f && f <= 1.0e6f) return (int)(f + 0.5f);
    return v;
}

// ---------------------------------------------------------------------------
// Kernel 1: build enc tables. blocks [0, MAXN) -> enc_i rows, [MAXN, 2*MAXN) -> enc_j.
// ---------------------------------------------------------------------------
__global__ void build_enc_kernel(const void* __restrict__ hp,
                                 const void* __restrict__ wp,
                                 const float* __restrict__ freqs_i,
                                 const float* __restrict__ freqs_j,
                                 int nf) {
    int h = read_dim(hp); if (h > MAXN) h = MAXN;
    int w = read_dim(wp); if (w > MAXN) w = MAXN;

    int row = blockIdx.x;
    bool is_j = (row >= MAXN);
    if (is_j) row -= MAXN;
    int n = is_j ? w : h;
    if (row >= n) return;

    const float* f = is_j ? freqs_j : freqs_i;
    float* dst = (is_j ? g_enc_j : g_enc_i) + (size_t)row * (2 * nf);
    float pos = (float)row;

    for (int k = threadIdx.x; k < nf; k += blockDim.x) {
        float s, c;
        sincosf(pos * f[k], &s, &c);   // precise sincos: args up to ~400 rad
        dst[2 * k]     = c;
        dst[2 * k + 1] = s;
    }
}

// ---------------------------------------------------------------------------
// Kernel 2 (vectorized): persistent grid-stride over 4x4 (i,j) tiles.
// 256 threads, each owns float4 chunks of D. Per tile: read (TI+TJ)*D floats
// (L2-resident), write TI*TJ*D floats fully coalesced.
// ---------------------------------------------------------------------------
__global__ void __launch_bounds__(256)
pe_tile_kernel_v4(const void* __restrict__ hp,
                  const void* __restrict__ wp,
                  float4* __restrict__ out,
                  int D) {
    const int h = read_dim(hp);
    const int w = read_dim(wp);
    const int D4 = D >> 2;
    const int nti = (h + TI - 1) / TI;
    const int ntj = (w + TJ - 1) / TJ;
    const int ntiles = nti * ntj;

    const float4* __restrict__ ei = (const float4*)g_enc_i;
    const float4* __restrict__ ej = (const float4*)g_enc_j;
    const float inv_max = 1.0f / 1000.0f;   // 1 / MAX_SEQ_LEN
    const float alpha = 0.1f;

    for (int t = blockIdx.x; t < ntiles; t += gridDim.x) {
        const int ti = t / ntj;
        const int tj = t - ti * ntj;
        const int i0 = ti * TI;
        const int j0 = tj * TJ;

        float sc[TI][TJ];
        #pragma unroll
        for (int a = 0; a < TI; a++) {
            float x = (float)(i0 + a) * inv_max;
            #pragma unroll
            for (int b = 0; b < TJ; b++) {
                float y = (float)(j0 + b) * inv_max;
                sc[a][b] = 1.0f + alpha * sqrtf(x * x + y * y);
            }
        }

        for (int v = threadIdx.x; v < D4; v += 256) {
            float4 ai[TI], bj[TJ];
            #pragma unroll
            for (int a = 0; a < TI; a++) {
                int ia = i0 + a; if (ia > h - 1) ia = h - 1;   // clamp OOB reads
                ai[a] = ei[(size_t)ia * D4 + v];
            }
            #pragma unroll
            for (int b = 0; b < TJ; b++) {
                int jb = j0 + b; if (jb > w - 1) jb = w - 1;
                bj[b] = ej[(size_t)jb * D4 + v];
            }

            #pragma unroll
            for (int a = 0; a < TI; a++) {
                if (i0 + a >= h) break;
                const size_t row_base = ((size_t)(i0 + a) * w) * D4;
                #pragma unroll
                for (int b = 0; b < TJ; b++) {
                    if (j0 + b >= w) break;
                    const float s = sc[a][b];
                    float4 r;
                    r.x = (ai[a].x + bj[b].x) * s;
                    r.y = (ai[a].y + bj[b].y) * s;
                    r.z = (ai[a].z + bj[b].z) * s;
                    r.w = (ai[a].w + bj[b].w) * s;
                    out[row_base + (size_t)(j0 + b) * D4 + v] = r;
                }
            }
        }
    }
}

// Scalar fallback for D % 4 != 0 (not expected here, D = 1024).
__global__ void __launch_bounds__(256)
pe_tile_kernel_scalar(const void* __restrict__ hp,
                      const void* __restrict__ wp,
                      float* __restrict__ out,
                      int D) {
    const int h = read_dim(hp);
    const int w = read_dim(wp);
    const int nti = (h + TI - 1) / TI;
    const int ntj = (w + TJ - 1) / TJ;
    const int ntiles = nti * ntj;
    const float inv_max = 1.0f / 1000.0f;

    for (int t = blockIdx.x; t < ntiles; t += gridDim.x) {
        const int ti = t / ntj;
        const int tj = t - ti * ntj;
        const int i0 = ti * TI;
        const int j0 = tj * TJ;

        for (int d = threadIdx.x; d < D; d += 256) {
            #pragma unroll
            for (int a = 0; a < TI; a++) {
                int i = i0 + a; if (i >= h) break;
                float vi = g_enc_i[(size_t)i * D + d];
                float x = (float)i * inv_max;
                #pragma unroll
                for (int b = 0; b < TJ; b++) {
                    int j = j0 + b; if (j >= w) break;
                    float y = (float)j * inv_max;
                    float s = 1.0f + 0.1f * sqrtf(x * x + y * y);
                    out[((size_t)i * w + j) * D + d] = (vi + g_enc_j[(size_t)j * D + d]) * s;
                }
            }
        }
    }
}

// ---------------------------------------------------------------------------
// Launch. Inputs (metadata order): height, width, freqs_i (nf), freqs_j (nf).
// Output: float32, out_size = h*w*2*nf elements.
// ---------------------------------------------------------------------------
extern "C" void kernel_launch(void* const* d_in, const int* in_sizes, int n_in,
                              void* d_out, int out_size) {
    const void* hp = d_in[0];
    const void* wp = d_in[1];
    const float* freqs_i = (const float*)d_in[2];
    const float* freqs_j = (const float*)d_in[3];
    const int nf = in_sizes[2];
    const int D = 2 * nf;

    // Kernel 1: fill enc tables (rows beyond h/w exit immediately).
    build_enc_kernel<<<2 * MAXN, 256>>>(hp, wp, freqs_i, freqs_j, nf);

    // Kernel 2: host knows h*w = out_size / D; grid-stride covers any tiling.
    const long long total_pairs = (long long)out_size / D;
    long long grid_ll = total_pairs / (TI * TJ) + 64;   // slack for ragged tiles
    if (grid_ll < 1) grid_ll = 1;
    if (grid_ll > (1 << 20)) grid_ll = (1 << 20);
    const int grid = (int)grid_ll;

    if ((D & 3) == 0) {
        pe_tile_kernel_v4<<<grid, 256>>>(hp, wp, (float4*)d_out, D);
    } else {
        pe_tile_kernel_scalar<<<grid, 256>>>(hp, wp, (float*)d_out, D);
    }
}

// round 2
// speedup vs baseline: 1.0366x; 1.0366x over previous
#include <cuda_runtime.h>
#include <cuda_bf16.h>
#include <math.h>

// ---------------------------------------------------------------------------
// ComplexExponentialPositionalEncoding
// out[i,j,:] = (enc_i[i,:] + enc_j[j,:]) * (1 + 0.1*sqrt((i/1000)^2 + (j/1000)^2))
// H=W=384, D=1024 -> 604MB fp32 output. Pure HBM-store-bound.
//
// R2: smem-tiled main kernel (TI=4 x TJ=8), 32-bit indexing,
//     launch_bounds(256,5) -> ~40 warps/SM vs 16 in R1.
// ---------------------------------------------------------------------------

#define MAXN 1024
#define MAXD 2048

__device__ float g_enc_i[(size_t)MAXN * MAXD];
__device__ float g_enc_j[(size_t)MAXN * MAXD];

__device__ __forceinline__ int read_dim(const void* p) {
    int v = *(const int*)p;
    if (v > 0 && v <= 1000000) return v;
    float f = *(const float*)p;
    if (f >= 1.0f && f <= 1.0e6f) return (int)(f + 0.5f);
    return v;
}

// ---------------------------------------------------------------------------
// Kernel 1: build enc tables.
// ---------------------------------------------------------------------------
__global__ void build_enc_kernel(const void* __restrict__ hp,
                                 const void* __restrict__ wp,
                                 const float* __restrict__ freqs_i,
                                 const float* __restrict__ freqs_j,
                                 int nf) {
    int h = read_dim(hp); if (h > MAXN) h = MAXN;
    int w = read_dim(wp); if (w > MAXN) w = MAXN;

    int row = blockIdx.x;
    bool is_j = (row >= MAXN);
    if (is_j) row -= MAXN;
    int n = is_j ? w : h;
    if (row >= n) return;

    const float* f = is_j ? freqs_j : freqs_i;
    float* dst = (is_j ? g_enc_j : g_enc_i) + (size_t)row * (2 * nf);
    float pos = (float)row;

    for (int k = threadIdx.x; k < nf; k += blockDim.x) {
        float s, c;
        sincosf(pos * f[k], &s, &c);
        dst[2 * k]     = c;
        dst[2 * k + 1] = s;
    }
}

// ---------------------------------------------------------------------------
// Kernel 2 (fast path, D == 1024): 4x8 (i,j) tile per CTA.
//   - enc_j tile (8 rows x 4KB) staged in smem (32KB)
//   - 32 per-tile scales staged in smem
//   - enc_i row chunk kept in 1 float4 reg per a-step
//   - 32-bit indexing throughout (out <= 2^31 float4 elements)
// Per tile: 48KB global reads (L2-hit), 128KB coalesced STG.128 writes.
// ---------------------------------------------------------------------------
#define FTI 4
#define FTJ 8
#define FD4 256   // D/4 for D=1024

__global__ void __launch_bounds__(256, 5)
pe_tile_kernel_1024(const void* __restrict__ hp,
                    const void* __restrict__ wp,
                    float4* __restrict__ out) {
    __shared__ float4 s_ej[FTJ][FD4];
    __shared__ float  s_sc[FTI][FTJ];

    const int h = read_dim(hp);
    const int w = read_dim(wp);
    const int nti = (h + FTI - 1) / FTI;
    const int ntj = (w + FTJ - 1) / FTJ;
    const int ntiles = nti * ntj;
    const int v = threadIdx.x;           // 0..255 == D4 lane

    const float4* __restrict__ ei = (const float4*)g_enc_i;
    const float4* __restrict__ ej = (const float4*)g_enc_j;
    const int wD4 = w * FD4;

    for (int t = blockIdx.x; t < ntiles; t += gridDim.x) {
        const int ti = t / ntj;
        const int tj = t - ti * ntj;
        const int i0 = ti * FTI;
        const int j0 = tj * FTJ;

        __syncthreads();   // protect smem reuse across grid-stride iterations

        // Stage enc_j tile (coalesced, L2-resident source).
        #pragma unroll
        for (int b = 0; b < FTJ; b++) {
            int jb = j0 + b; if (jb > w - 1) jb = w - 1;
            s_ej[b][v] = ej[jb * FD4 + v];
        }
        // Stage the 32 tile scales.
        if (v < FTI * FTJ) {
            const int a = v >> 3, b = v & 7;
            const float x = (float)(i0 + a) * (1.0f / 1000.0f);
            const float y = (float)(j0 + b) * (1.0f / 1000.0f);
            s_sc[a][b] = 1.0f + 0.1f * sqrtf(x * x + y * y);
        }
        __syncthreads();

        #pragma unroll
        for (int a = 0; a < FTI; a++) {
            const int ia = i0 + a;
            if (ia >= h) break;
            const float4 av = ei[ia * FD4 + v];
            float4* __restrict__ orow = out + (ia * wD4 + j0 * FD4 + v);
            #pragma unroll
            for (int b = 0; b < FTJ; b++) {
                if (j0 + b >= w) break;
                const float s = s_sc[a][b];
                const float4 e = s_ej[b][v];
                float4 r;
                r.x = (av.x + e.x) * s;
                r.y = (av.y + e.y) * s;
                r.z = (av.z + e.z) * s;
                r.w = (av.w + e.w) * s;
                orow[b * FD4] = r;
            }
        }
    }
}

// ---------------------------------------------------------------------------
// General fallback kernels (any D): R1 versions.
// ---------------------------------------------------------------------------
#define TI 4
#define TJ 4

__global__ void __launch_bounds__(256)
pe_tile_kernel_v4(const void* __restrict__ hp,
                  const void* __restrict__ wp,
                  float4* __restrict__ out,
                  int D) {
    const int h = read_dim(hp);
    const int w = read_dim(wp);
    const int D4 = D >> 2;
    const int nti = (h + TI - 1) / TI;
    const int ntj = (w + TJ - 1) / TJ;
    const int ntiles = nti * ntj;

    const float4* __restrict__ ei = (const float4*)g_enc_i;
    const float4* __restrict__ ej = (const float4*)g_enc_j;
    const float inv_max = 1.0f / 1000.0f;
    const float alpha = 0.1f;

    for (int t = blockIdx.x; t < ntiles; t += gridDim.x) {
        const int ti = t / ntj;
        const int tj = t - ti * ntj;
        const int i0 = ti * TI;
        const int j0 = tj * TJ;

        float sc[TI][TJ];
        #pragma unroll
        for (int a = 0; a < TI; a++) {
            float x = (float)(i0 + a) * inv_max;
            #pragma unroll
            for (int b = 0; b < TJ; b++) {
                float y = (float)(j0 + b) * inv_max;
                sc[a][b] = 1.0f + alpha * sqrtf(x * x + y * y);
            }
        }

        for (int vv = threadIdx.x; vv < D4; vv += 256) {
            float4 ai[TI], bj[TJ];
            #pragma unroll
            for (int a = 0; a < TI; a++) {
                int ia = i0 + a; if (ia > h - 1) ia = h - 1;
                ai[a] = ei[(size_t)ia * D4 + vv];
            }
            #pragma unroll
            for (int b = 0; b < TJ; b++) {
                int jb = j0 + b; if (jb > w - 1) jb = w - 1;
                bj[b] = ej[(size_t)jb * D4 + vv];
            }

            #pragma unroll
            for (int a = 0; a < TI; a++) {
                if (i0 + a >= h) break;
                const size_t row_base = ((size_t)(i0 + a) * w) * D4;
                #pragma unroll
                for (int b = 0; b < TJ; b++) {
                    if (j0 + b >= w) break;
                    const float s = sc[a][b];
                    float4 r;
                    r.x = (ai[a].x + bj[b].x) * s;
                    r.y = (ai[a].y + bj[b].y) * s;
                    r.z = (ai[a].z + bj[b].z) * s;
                    r.w = (ai[a].w + bj[b].w) * s;
                    out[row_base + (size_t)(j0 + b) * D4 + vv] = r;
                }
            }
        }
    }
}

__global__ void __launch_bounds__(256)
pe_tile_kernel_scalar(const void* __restrict__ hp,
                      const void* __restrict__ wp,
                      float* __restrict__ out,
                      int D) {
    const int h = read_dim(hp);
    const int w = read_dim(wp);
    const int nti = (h + TI - 1) / TI;
    const int ntj = (w + TJ - 1) / TJ;
    const int ntiles = nti * ntj;
    const float inv_max = 1.0f / 1000.0f;

    for (int t = blockIdx.x; t < ntiles; t += gridDim.x) {
        const int ti = t / ntj;
        const int tj = t - ti * ntj;
        const int i0 = ti * TI;
        const int j0 = tj * TJ;

        for (int d = threadIdx.x; d < D; d += 256) {
            #pragma unroll
            for (int a = 0; a < TI; a++) {
                int i = i0 + a; if (i >= h) break;
                float vi = g_enc_i[(size_t)i * D + d];
                float x = (float)i * inv_max;
                #pragma unroll
                for (int b = 0; b < TJ; b++) {
                    int j = j0 + b; if (j >= w) break;
                    float y = (float)j * inv_max;
                    float s = 1.0f + 0.1f * sqrtf(x * x + y * y);
                    out[((size_t)i * w + j) * D + d] = (vi + g_enc_j[(size_t)j * D + d]) * s;
                }
            }
        }
    }
}

// ---------------------------------------------------------------------------
// Launch. Inputs: height, width, freqs_i (nf), freqs_j (nf). Output: fp32.
// ---------------------------------------------------------------------------
extern "C" void kernel_launch(void* const* d_in, const int* in_sizes, int n_in,
                              void* d_out, int out_size) {
    const void* hp = d_in[0];
    const void* wp = d_in[1];
    const float* freqs_i = (const float*)d_in[2];
    const float* freqs_j = (const float*)d_in[3];
    const int nf = in_sizes[2];
    const int D = 2 * nf;

    build_enc_kernel<<<2 * MAXN, 256>>>(hp, wp, freqs_i, freqs_j, nf);

    const long long total_pairs = (long long)out_size / D;   // == h*w

    if (D == 1024) {
        long long ntiles = total_pairs / (FTI * FTJ) + 64;   // slack for ragged tiles
        if (ntiles < 1) ntiles = 1;
        if (ntiles > (1 << 20)) ntiles = (1 << 20);
        pe_tile_kernel_1024<<<(int)ntiles, 256>>>(hp, wp, (float4*)d_out);
    } else if ((D & 3) == 0) {
        long long grid_ll = total_pairs / (TI * TJ) + 64;
        if (grid_ll < 1) grid_ll = 1;
        if (grid_ll > (1 << 20)) grid_ll = (1 << 20);
        pe_tile_kernel_v4<<<(int)grid_ll, 256>>>(hp, wp, (float4*)d_out, D);
    } else {
        long long grid_ll = total_pairs / (TI * TJ) + 64;
        if (grid_ll < 1) grid_ll = 1;
        if (grid_ll > (1 << 20)) grid_ll = (1 << 20);
        pe_tile_kernel_scalar<<<(int)grid_ll, 256>>>(hp, wp, (float*)d_out, D);
    }
}

// round 3
// speedup vs baseline: 1.0641x; 1.0265x over previous
#include <cuda_runtime.h>
#include <cuda_bf16.h>
#include <math.h>

// ---------------------------------------------------------------------------
// ComplexExponentialPositionalEncoding
// out[i,j,:] = (enc_i[i,:] + enc_j[j,:]) * (1 + 0.1*sqrt((i/1000)^2 + (j/1000)^2))
// H=W=384, D=1024 -> 604MB fp32 output. Pure HBM-store-bound.
//
// R3: TI=8 x TJ=8 tile (read:write ratio 0.25), streaming stores (__stcs),
//     same smem staging of enc_j + scales, 32-bit indexing.
// ---------------------------------------------------------------------------

#define MAXN 1024
#define MAXD 2048

__device__ float g_enc_i[(size_t)MAXN * MAXD];
__device__ float g_enc_j[(size_t)MAXN * MAXD];

__device__ __forceinline__ int read_dim(const void* p) {
    int v = *(const int*)p;
    if (v > 0 && v <= 1000000) return v;
    float f = *(const float*)p;
    if (f >= 1.0f && f <= 1.0e6f) return (int)(f + 0.5f);
    return v;
}

// ---------------------------------------------------------------------------
// Kernel 1: build enc tables.
// ---------------------------------------------------------------------------
__global__ void build_enc_kernel(const void* __restrict__ hp,
                                 const void* __restrict__ wp,
                                 const float* __restrict__ freqs_i,
                                 const float* __restrict__ freqs_j,
                                 int nf) {
    int h = read_dim(hp); if (h > MAXN) h = MAXN;
    int w = read_dim(wp); if (w > MAXN) w = MAXN;

    int row = blockIdx.x;
    bool is_j = (row >= MAXN);
    if (is_j) row -= MAXN;
    int n = is_j ? w : h;
    if (row >= n) return;

    const float* f = is_j ? freqs_j : freqs_i;
    float* dst = (is_j ? g_enc_j : g_enc_i) + (size_t)row * (2 * nf);
    float pos = (float)row;

    for (int k = threadIdx.x; k < nf; k += blockDim.x) {
        float s, c;
        sincosf(pos * f[k], &s, &c);
        dst[2 * k]     = c;
        dst[2 * k + 1] = s;
    }
}

// ---------------------------------------------------------------------------
// Kernel 2 (fast path, D == 1024): 8x8 (i,j) tile per CTA.
//   - enc_j tile (8 rows x 4KB) staged in smem (32KB)
//   - 64 per-tile scales staged in smem
//   - enc_i row chunk: 1 float4 LDG per a-step (L2 hit)
//   - streaming 128-bit stores (__stcs): output is write-once
// Per tile: 64KB global reads (L2-hit), 256KB coalesced streaming writes.
// ---------------------------------------------------------------------------
#define FTI 8
#define FTJ 8
#define FD4 256   // D/4 for D=1024

__global__ void __launch_bounds__(256, 5)
pe_tile_kernel_1024(const void* __restrict__ hp,
                    const void* __restrict__ wp,
                    float4* __restrict__ out) {
    __shared__ float4 s_ej[FTJ][FD4];
    __shared__ float  s_sc[FTI][FTJ];

    const int h = read_dim(hp);
    const int w = read_dim(wp);
    const int nti = (h + FTI - 1) / FTI;
    const int ntj = (w + FTJ - 1) / FTJ;
    const int ntiles = nti * ntj;
    const int v = threadIdx.x;           // 0..255 == D4 lane

    const float4* __restrict__ ei = (const float4*)g_enc_i;
    const float4* __restrict__ ej = (const float4*)g_enc_j;
    const int wD4 = w * FD4;

    for (int t = blockIdx.x; t < ntiles; t += gridDim.x) {
        const int ti = t / ntj;
        const int tj = t - ti * ntj;
        const int i0 = ti * FTI;
        const int j0 = tj * FTJ;

        __syncthreads();   // protect smem reuse across grid-stride iterations

        // Stage enc_j tile (coalesced, L2-resident source).
        #pragma unroll
        for (int b = 0; b < FTJ; b++) {
            int jb = j0 + b; if (jb > w - 1) jb = w - 1;
            s_ej[b][v] = ej[jb * FD4 + v];
        }
        // Stage the 64 tile scales.
        if (v < FTI * FTJ) {
            const int a = v >> 3, b = v & 7;
            const float x = (float)(i0 + a) * (1.0f / 1000.0f);
            const float y = (float)(j0 + b) * (1.0f / 1000.0f);
            s_sc[a][b] = 1.0f + 0.1f * sqrtf(x * x + y * y);
        }
        __syncthreads();

        #pragma unroll
        for (int a = 0; a < FTI; a++) {
            const int ia = i0 + a;
            if (ia >= h) break;
            const float4 av = ei[ia * FD4 + v];
            float4* __restrict__ orow = out + (ia * wD4 + j0 * FD4 + v);
            #pragma unroll
            for (int b = 0; b < FTJ; b++) {
                if (j0 + b >= w) break;
                const float s = s_sc[a][b];
                const float4 e = s_ej[b][v];
                float4 r;
                r.x = (av.x + e.x) * s;
                r.y = (av.y + e.y) * s;
                r.z = (av.z + e.z) * s;
                r.w = (av.w + e.w) * s;
                __stcs(&orow[b * FD4], r);   // streaming: evict-first
            }
        }
    }
}

// ---------------------------------------------------------------------------
// General fallback kernels (any D).
// ---------------------------------------------------------------------------
#define TI 4
#define TJ 4

__global__ void __launch_bounds__(256)
pe_tile_kernel_v4(const void* __restrict__ hp,
                  const void* __restrict__ wp,
                  float4* __restrict__ out,
                  int D) {
    const int h = read_dim(hp);
    const int w = read_dim(wp);
    const int D4 = D >> 2;
    const int nti = (h + TI - 1) / TI;
    const int ntj = (w + TJ - 1) / TJ;
    const int ntiles = nti * ntj;

    const float4* __restrict__ ei = (const float4*)g_enc_i;
    const float4* __restrict__ ej = (const float4*)g_enc_j;
    const float inv_max = 1.0f / 1000.0f;
    const float alpha = 0.1f;

    for (int t = blockIdx.x; t < ntiles; t += gridDim.x) {
        const int ti = t / ntj;
        const int tj = t - ti * ntj;
        const int i0 = ti * TI;
        const int j0 = tj * TJ;

        float sc[TI][TJ];
        #pragma unroll
        for (int a = 0; a < TI; a++) {
            float x = (float)(i0 + a) * inv_max;
            #pragma unroll
            for (int b = 0; b < TJ; b++) {
                float y = (float)(j0 + b) * inv_max;
                sc[a][b] = 1.0f + alpha * sqrtf(x * x + y * y);
            }
        }

        for (int vv = threadIdx.x; vv < D4; vv += 256) {
            float4 ai[TI], bj[TJ];
            #pragma unroll
            for (int a = 0; a < TI; a++) {
                int ia = i0 + a; if (ia > h - 1) ia = h - 1;
                ai[a] = ei[(size_t)ia * D4 + vv];
            }
            #pragma unroll
            for (int b = 0; b < TJ; b++) {
                int jb = j0 + b; if (jb > w - 1) jb = w - 1;
                bj[b] = ej[(size_t)jb * D4 + vv];
            }

            #pragma unroll
            for (int a = 0; a < TI; a++) {
                if (i0 + a >= h) break;
                const size_t row_base = ((size_t)(i0 + a) * w) * D4;
                #pragma unroll
                for (int b = 0; b < TJ; b++) {
                    if (j0 + b >= w) break;
                    const float s = sc[a][b];
                    float4 r;
                    r.x = (ai[a].x + bj[b].x) * s;
                    r.y = (ai[a].y + bj[b].y) * s;
                    r.z = (ai[a].z + bj[b].z) * s;
                    r.w = (ai[a].w + bj[b].w) * s;
                    out[row_base + (size_t)(j0 + b) * D4 + vv] = r;
                }
            }
        }
    }
}

__global__ void __launch_bounds__(256)
pe_tile_kernel_scalar(const void* __restrict__ hp,
                      const void* __restrict__ wp,
                      float* __restrict__ out,
                      int D) {
    const int h = read_dim(hp);
    const int w = read_dim(wp);
    const int nti = (h + TI - 1) / TI;
    const int ntj = (w + TJ - 1) / TJ;
    const int ntiles = nti * ntj;
    const float inv_max = 1.0f / 1000.0f;

    for (int t = blockIdx.x; t < ntiles; t += gridDim.x) {
        const int ti = t / ntj;
        const int tj = t - ti * ntj;
        const int i0 = ti * TI;
        const int j0 = tj * TJ;

        for (int d = threadIdx.x; d < D; d += 256) {
            #pragma unroll
            for (int a = 0; a < TI; a++) {
                int i = i0 + a; if (i >= h) break;
                float vi = g_enc_i[(size_t)i * D + d];
                float x = (float)i * inv_max;
                #pragma unroll
                for (int b = 0; b < TJ; b++) {
                    int j = j0 + b; if (j >= w) break;
                    float y = (float)j * inv_max;
                    float s = 1.0f + 0.1f * sqrtf(x * x + y * y);
                    out[((size_t)i * w + j) * D + d] = (vi + g_enc_j[(size_t)j * D + d]) * s;
                }
            }
        }
    }
}

// ---------------------------------------------------------------------------
// Launch. Inputs: height, width, freqs_i (nf), freqs_j (nf). Output: fp32.
// ---------------------------------------------------------------------------
extern "C" void kernel_launch(void* const* d_in, const int* in_sizes, int n_in,
                              void* d_out, int out_size) {
    const void* hp = d_in[0];
    const void* wp = d_in[1];
    const float* freqs_i = (const float*)d_in[2];
    const float* freqs_j = (const float*)d_in[3];
    const int nf = in_sizes[2];
    const int D = 2 * nf;

    build_enc_kernel<<<2 * MAXN, 256>>>(hp, wp, freqs_i, freqs_j, nf);

    const long long total_pairs = (long long)out_size / D;   // == h*w

    if (D == 1024) {
        long long ntiles = total_pairs / (FTI * FTJ) + 64;   // slack for ragged tiles
        if (ntiles < 1) ntiles = 1;
        if (ntiles > (1 << 20)) ntiles = (1 << 20);
        pe_tile_kernel_1024<<<(int)ntiles, 256>>>(hp, wp, (float4*)d_out);
    } else if ((D & 3) == 0) {
        long long grid_ll = total_pairs / (TI * TJ) + 64;
        if (grid_ll < 1) grid_ll = 1;
        if (grid_ll > (1 << 20)) grid_ll = (1 << 20);
        pe_tile_kernel_v4<<<(int)grid_ll, 256>>>(hp, wp, (float4*)d_out, D);
    } else {
        long long grid_ll = total_pairs / (TI * TJ) + 64;
        if (grid_ll < 1) grid_ll = 1;
        if (grid_ll > (1 << 20)) grid_ll = (1 << 20);
        pe_tile_kernel_scalar<<<(int)grid_ll, 256>>>(hp, wp, (float*)d_out, D);
    }
}